// round 15
// baseline (speedup 1.0000x reference)
#include <cuda_runtime.h>
#include <cuda_fp16.h>
#include <math.h>

namespace {
constexpr int kS = 2048, kB = 2, kD = 1024, kH = 16, kDh = 64;
constexpr int kRows = kS * kB;            // 4096
constexpr float kScale = 0.125f;          // 1/sqrt(64), folded into q + BD consts
constexpr float kEps = 1e-5f;
constexpr int kRkChunks = 16;
// prologue block ranges
constexpr int kNbLn  = kRows;                       // 4096
constexpr int kNbCw0 = (3 * kD / 32) * (kD / 32);   // 3072
constexpr int kNbCw1 = (kD / 32) * (kD / 32);       // 1024
constexpr int kNbRk  = (kD / 256) * kRkChunks;      // 64
}

// ------------------------- scratch (static device memory) -------------------
// NOTE: only referenced inside device code — never passed as kernel args.
__device__ float  g_xn[kRows * kD];
__device__ __half g_xn_h[kRows * kD];
__device__ __half g_wqkv_t[3 * kD * kD];           // Wqkv^T [n][k]
__device__ __half g_wo_t[kD * kD];                 // Wo^T [n][k]
__device__ __half g_q[kB * kH * kS * kDh];         // (q + rw) * kScale  [b][h][s][d]
__device__ __half g_k[kB * kH * kS * kDh];         // [b][h][s][d]
__device__ __half g_v[kB * kH * kS * kDh];         // [b][h][s][d]
__device__ __half g_av[kRows * kD];
__device__ float  g_rk0p[kRkChunks * kD];
__device__ float  g_rk0[kD];

// ------------------------------ asm helpers ----------------------------------
__device__ __forceinline__ void mma16816(float* c, const unsigned* a, const unsigned* b) {
    asm volatile(
        "mma.sync.aligned.m16n8k16.row.col.f32.f16.f16.f32 "
        "{%0,%1,%2,%3},{%4,%5,%6,%7},{%8,%9},{%0,%1,%2,%3};\n"
        : "+f"(c[0]), "+f"(c[1]), "+f"(c[2]), "+f"(c[3])
        : "r"(a[0]), "r"(a[1]), "r"(a[2]), "r"(a[3]), "r"(b[0]), "r"(b[1]));
}
__device__ __forceinline__ void ldsm_x4(unsigned* r, unsigned addr) {
    asm volatile("ldmatrix.sync.aligned.m8n8.x4.shared.b16 {%0,%1,%2,%3}, [%4];\n"
                 : "=r"(r[0]), "=r"(r[1]), "=r"(r[2]), "=r"(r[3]) : "r"(addr));
}
__device__ __forceinline__ void ldsm_x4_trans(unsigned* r, unsigned addr) {
    asm volatile("ldmatrix.sync.aligned.m8n8.x4.trans.shared.b16 {%0,%1,%2,%3}, [%4];\n"
                 : "=r"(r[0]), "=r"(r[1]), "=r"(r[2]), "=r"(r[3]) : "r"(addr));
}
__device__ __forceinline__ unsigned smem_u32(const void* p) {
    return (unsigned)__cvta_generic_to_shared(p);
}
__device__ __forceinline__ void cp_async16(unsigned dst, const void* src) {
    asm volatile("cp.async.cg.shared.global [%0], [%1], 16;\n"
                 :: "r"(dst), "l"(__cvta_generic_to_global(src)));
}
#define CP_COMMIT() asm volatile("cp.async.commit_group;\n")
#define CP_WAIT(n)  asm volatile("cp.async.wait_group %0;\n" :: "n"(n))

// ------------------- fused prologue: ln | convw0 | convw1 | rk0_part ---------
__global__ __launch_bounds__(256) void prologue_kernel(
        const float* __restrict__ x, const float* __restrict__ gamma,
        const float* __restrict__ beta, const float* __restrict__ Wqkv,
        const float* __restrict__ Wo, const float* __restrict__ r,
        const float* __restrict__ Wr) {
    __shared__ float tile[32][33];
    __shared__ float sm1[8], sm2[8];
    int blk = blockIdx.x;
    int tid = threadIdx.x;

    if (blk < kNbLn) {
        // ---------------- LayerNorm ----------------
        int row = blk, t = tid;
        const float4 v = reinterpret_cast<const float4*>(x + (size_t)row * kD)[t];
        float s1 = v.x + v.y + v.z + v.w;
        float s2 = v.x*v.x + v.y*v.y + v.z*v.z + v.w*v.w;
        #pragma unroll
        for (int o = 16; o; o >>= 1) {
            s1 += __shfl_xor_sync(~0u, s1, o);
            s2 += __shfl_xor_sync(~0u, s2, o);
        }
        int w = t >> 5, lane = t & 31;
        if (lane == 0) { sm1[w] = s1; sm2[w] = s2; }
        __syncthreads();
        if (w == 0) {
            s1 = (lane < 8) ? sm1[lane] : 0.f;
            s2 = (lane < 8) ? sm2[lane] : 0.f;
            #pragma unroll
            for (int o = 4; o; o >>= 1) {
                s1 += __shfl_xor_sync(~0u, s1, o);
                s2 += __shfl_xor_sync(~0u, s2, o);
            }
            if (lane == 0) { sm1[0] = s1; sm2[0] = s2; }
        }
        __syncthreads();
        float mu = sm1[0] * (1.f / kD);
        float var = sm2[0] * (1.f / kD) - mu * mu;
        float rstd = rsqrtf(var + kEps);
        const float4 gv = reinterpret_cast<const float4*>(gamma)[t];
        const float4 bv = reinterpret_cast<const float4*>(beta)[t];
        float4 o;
        o.x = (v.x - mu) * rstd * gv.x + bv.x;
        o.y = (v.y - mu) * rstd * gv.y + bv.y;
        o.z = (v.z - mu) * rstd * gv.z + bv.z;
        o.w = (v.w - mu) * rstd * gv.w + bv.w;
        reinterpret_cast<float4*>(g_xn + (size_t)row * kD)[t] = o;
        *reinterpret_cast<__half2*>(&g_xn_h[(size_t)row * kD + t * 4])     = __floats2half2_rn(o.x, o.y);
        *reinterpret_cast<__half2*>(&g_xn_h[(size_t)row * kD + t * 4 + 2]) = __floats2half2_rn(o.z, o.w);
    } else if (blk < kNbLn + kNbCw0 + kNbCw1) {
        // ---------------- weight transpose + cast ----------------
        bool first = (blk < kNbLn + kNbCw0);
        int local = first ? (blk - kNbLn) : (blk - kNbLn - kNbCw0);
        int N = first ? 3 * kD : kD;
        const float* src = first ? Wqkv : Wo;
        __half* dst = first ? g_wqkv_t : g_wo_t;
        int nt = N / 32;
        int bx = local % nt, by = local / nt;
        int n0 = bx * 32, k0 = by * 32;
        int tx = tid & 31, ty = tid >> 5;
        #pragma unroll
        for (int i = 0; i < 32; i += 8)
            tile[ty + i][tx] = src[(size_t)(k0 + ty + i) * N + n0 + tx];
        __syncthreads();
        #pragma unroll
        for (int i = 0; i < 32; i += 8)
            dst[(size_t)(n0 + ty + i) * kD + k0 + tx] = __float2half(tile[tx][ty + i]);
    } else {
        // ---------------- rk0 partial ----------------
        int local = blk - (kNbLn + kNbCw0 + kNbCw1);
        int chunk = local >> 2, colblk = local & 3;
        int col = colblk * 256 + tid;
        int d0 = chunk * (kD / kRkChunks);
        float s = 0.f;
        #pragma unroll
        for (int i = 0; i < kD / kRkChunks; i++)
            s += r[d0 + i] * Wr[(size_t)(d0 + i) * kD + col];
        g_rk0p[chunk * kD + col] = s;
    }
}

__global__ void rk0_reduce_kernel() {
    int col = blockIdx.x * 256 + threadIdx.x;
    float s = 0.f;
    #pragma unroll
    for (int c = 0; c < kRkChunks; c++) s += g_rk0p[c * kD + col];
    g_rk0[col] = s;
}

// ------------------------------ QKV GEMM (fp16 mma, cp.async + ldmatrix) -----
__global__ __launch_bounds__(256) void gemm_qkv_kernel(const float* __restrict__ rw) {
    __shared__ __half As[2][128][40];
    __shared__ __half Bs[2][128][40];
    int tid = threadIdx.x, lane = tid & 31, w = tid >> 5;
    int gid = lane >> 2, tig = lane & 3;
    int m0 = blockIdx.y * 128, n0 = blockIdx.x * 128;
    int wm = w >> 2, wn = w & 3;
    constexpr unsigned stageB = 128 * 40 * 2;
    unsigned a_base = smem_u32(&As[0][wm * 64 + (lane & 15)][(lane >> 4) * 8]);
    unsigned b_base = smem_u32(&Bs[0][wn * 32 + (lane & 7) + ((lane >> 4) << 3)][((lane >> 3) & 1) * 8]);
    int lr = tid >> 2, lc = (tid & 3) * 8;
    int lr2 = lr + 64;
    float acc[4][4][4] = {};

    cp_async16(smem_u32(&As[0][lr][lc]),  &g_xn_h[(size_t)(m0 + lr) * kD + lc]);
    cp_async16(smem_u32(&As[0][lr2][lc]), &g_xn_h[(size_t)(m0 + lr2) * kD + lc]);
    cp_async16(smem_u32(&Bs[0][lr][lc]),  &g_wqkv_t[(size_t)(n0 + lr) * kD + lc]);
    cp_async16(smem_u32(&Bs[0][lr2][lc]), &g_wqkv_t[(size_t)(n0 + lr2) * kD + lc]);
    CP_COMMIT();

    constexpr int NIT = kD / 32;
    for (int it = 0; it < NIT; it++) {
        if (it + 1 < NIT) {
            int st = (it + 1) & 1, k0 = (it + 1) * 32;
            cp_async16(smem_u32(&As[st][lr][lc]),  &g_xn_h[(size_t)(m0 + lr) * kD + k0 + lc]);
            cp_async16(smem_u32(&As[st][lr2][lc]), &g_xn_h[(size_t)(m0 + lr2) * kD + k0 + lc]);
            cp_async16(smem_u32(&Bs[st][lr][lc]),  &g_wqkv_t[(size_t)(n0 + lr) * kD + k0 + lc]);
            cp_async16(smem_u32(&Bs[st][lr2][lc]), &g_wqkv_t[(size_t)(n0 + lr2) * kD + k0 + lc]);
            CP_COMMIT();
            CP_WAIT(1);
        } else {
            CP_WAIT(0);
        }
        __syncthreads();
        unsigned soff = (it & 1) * stageB;
        #pragma unroll
        for (int kb = 0; kb < 32; kb += 16) {
            unsigned a[4][4], b[2][4];
            #pragma unroll
            for (int mi = 0; mi < 4; mi++)
                ldsm_x4(a[mi], a_base + soff + (mi * 16 * 40 + kb) * 2);
            #pragma unroll
            for (int p = 0; p < 2; p++)
                ldsm_x4(b[p], b_base + soff + (p * 16 * 40 + kb) * 2);
            #pragma unroll
            for (int mi = 0; mi < 4; mi++)
                #pragma unroll
                for (int p = 0; p < 2; p++) {
                    mma16816(acc[mi][2 * p],     a[mi], b[p]);
                    mma16816(acc[mi][2 * p + 1], a[mi], b[p] + 2);
                }
        }
        __syncthreads();
    }
    // epilogue: scatter to q(+rw, *kScale)/k/v (all coalesced __half2)
    #pragma unroll
    for (int mi = 0; mi < 4; mi++) {
        int r0e = m0 + wm * 64 + mi * 16 + gid, r1e = r0e + 8;
        int s0 = r0e >> 1, b0e = r0e & 1;
        int s1 = r1e >> 1, b1e = r1e & 1;
        #pragma unroll
        for (int ni = 0; ni < 4; ni++) {
            int c0 = n0 + wn * 32 + ni * 8 + tig * 2;
            int part = c0 >> 10, rem = c0 & 1023, hh = rem >> 6, d = rem & 63;
            size_t di0 = (((size_t)(b0e * kH + hh)) * kS + s0) * kDh + d;
            size_t di1 = (((size_t)(b1e * kH + hh)) * kS + s1) * kDh + d;
            float v00 = acc[mi][ni][0], v01 = acc[mi][ni][1];
            float v10 = acc[mi][ni][2], v11 = acc[mi][ni][3];
            if (part == 0) {
                float w0 = rw[rem], w1 = rw[rem + 1];
                *(__half2*)&g_q[di0] =
                    __floats2half2_rn((v00 + w0) * kScale, (v01 + w1) * kScale);
                *(__half2*)&g_q[di1] =
                    __floats2half2_rn((v10 + w0) * kScale, (v11 + w1) * kScale);
            } else if (part == 1) {
                *(__half2*)&g_k[di0] = __floats2half2_rn(v00, v01);
                *(__half2*)&g_k[di1] = __floats2half2_rn(v10, v11);
            } else {
                *(__half2*)&g_v[di0] = __floats2half2_rn(v00, v01);
                *(__half2*)&g_v[di1] = __floats2half2_rn(v10, v11);
            }
        }
    }
}

// ------------- Flash attention (fp16 mma, 64q/4warp, reg-Q/P, fused cbd) -----
// Block: 128 thr = 4 warps, one (b,h), 64 query rows (16/warp), key tiles 64.
// q is pre-scaled by kScale, so S and BD constants need no further scaling.
__global__ __launch_bounds__(128) void flash_kernel(const float* __restrict__ rw,
                                                    const float* __restrict__ rr) {
    __shared__ __half Ks[2][64][72];
    __shared__ __half Vs[2][64][72];       // natural [j][d]
    __shared__ float csm[68];              // [0..64]=row dots (scaled), [66]=C_h
    int b = blockIdx.z, h = blockIdx.y, i0 = blockIdx.x * 64;
    int tid = threadIdx.x, w = tid >> 5, lane = tid & 31;
    int gid = lane >> 2, tig = lane & 3;
    size_t base = ((size_t)(b * kH + h)) * kS * kDh;

    // ---- stage Q through Ks[0] (64 rows x 72 stride), capture frags + dots --
    __half* qstage = &Ks[0][0][0];
    #pragma unroll
    for (int t = 0; t < 4; t++) {
        int idx = tid + t * 128;
        int r = idx >> 3, c = (idx & 7) * 8;
        *(float4*)&qstage[r * 72 + c] = *(const float4*)&g_q[base + (size_t)(i0 + r) * kDh + c];
    }
    __syncthreads();
    unsigned qf[4][4];
    {
        unsigned qa = smem_u32(qstage + (w * 16 + (lane & 15)) * 72 + (lane >> 4) * 8);
        #pragma unroll
        for (int c4 = 0; c4 < 4; c4++) ldsm_x4(qf[c4], qa + c4 * 32);
    }
    // C_h = kScale * sum_d (rr - rw) * rk0   (warp 0)
    if (w == 0) {
        int hd = h * kDh + lane;
        float chs = (rr[hd] - rw[hd]) * g_rk0[hd]
                  + (rr[hd + 32] - rw[hd + 32]) * g_rk0[hd + 32];
        #pragma unroll
        for (int o = 16; o; o >>= 1) chs += __shfl_xor_sync(~0u, chs, o);
        if (lane == 0) csm[66] = chs * kScale;
    }
    // row dots: csm[r] = q_scaled_row . rk0  (pairs of threads per row)
    {
        int rrow = tid >> 1, halfsel = (tid & 1) * 32;
        const __half* qr = qstage + rrow * 72 + halfsel;
        const float* rk = g_rk0 + h * kDh + halfsel;
        float p = 0.f;
        #pragma unroll
        for (int d = 0; d < 32; d++) p += __half2float(qr[d]) * rk[d];
        p += __shfl_xor_sync(~0u, p, 1);
        if ((tid & 1) == 0) csm[rrow] = p;
    }
    // boundary row i0+64 (from gmem, already scaled)
    if (tid < 2) {
        int gi = i0 + 64;
        float p = 0.f;
        if (gi < kS) {
            const __half* qr = &g_q[base + (size_t)gi * kDh + tid * 32];
            const float* rk = g_rk0 + h * kDh + tid * 32;
            #pragma unroll
            for (int d = 0; d < 32; d++) p += __half2float(qr[d]) * rk[d];
        }
        p += __shfl_xor_sync(0x3u, p, 1);
        if (tid == 0) csm[64] = p;
    }
    __syncthreads();   // Q captured + csm ready; K buffer reusable

    float Ch = csm[66];
    int lr0 = w * 16 + gid;
    int r0 = i0 + lr0, r1 = r0 + 8;
    float cA  = csm[lr0] + Ch;
    float cA1 = (r0 + 1 < kS) ? csm[lr0 + 1] + Ch : 0.f;
    float cB  = csm[lr0 + 8] + Ch;
    float cB1 = (r1 + 1 < kS) ? csm[lr0 + 9] + Ch : 0.f;

    unsigned ka_base = smem_u32(&Ks[0][(lane & 7) + ((lane >> 4) << 3)][((lane >> 3) & 1) * 8]);
    unsigned va_base = smem_u32(&Vs[0][(lane & 7) + (((lane >> 3) & 1) << 3)][(lane >> 4) * 8]);
    constexpr unsigned stageB = 64 * 72 * 2;

    float m0v = -1e30f, m1v = -1e30f, l0 = 0.f, l1 = 0.f;
    float o[8][4] = {};

    // pipeline loader: 64 rows x 64 halfs = 512 chunks/array; 128 thr x 4 chunks
    int plr = tid >> 1, pc0 = (tid & 1) * 32;
    {
        size_t roff = base + (size_t)plr * kDh + pc0;
        cp_async16(smem_u32(&Ks[0][plr][pc0]),      &g_k[roff]);
        cp_async16(smem_u32(&Ks[0][plr][pc0 + 8]),  &g_k[roff + 8]);
        cp_async16(smem_u32(&Ks[0][plr][pc0 + 16]), &g_k[roff + 16]);
        cp_async16(smem_u32(&Ks[0][plr][pc0 + 24]), &g_k[roff + 24]);
        cp_async16(smem_u32(&Vs[0][plr][pc0]),      &g_v[roff]);
        cp_async16(smem_u32(&Vs[0][plr][pc0 + 8]),  &g_v[roff + 8]);
        cp_async16(smem_u32(&Vs[0][plr][pc0 + 16]), &g_v[roff + 16]);
        cp_async16(smem_u32(&Vs[0][plr][pc0 + 24]), &g_v[roff + 24]);
        CP_COMMIT();
    }

    constexpr int NT = kS / 64;
    for (int jt = 0; jt < NT; jt++) {
        if (jt + 1 < NT) {
            int st = (jt + 1) & 1;
            size_t roff = base + (size_t)((jt + 1) * 64 + plr) * kDh + pc0;
            cp_async16(smem_u32(&Ks[st][plr][pc0]),      &g_k[roff]);
            cp_async16(smem_u32(&Ks[st][plr][pc0 + 8]),  &g_k[roff + 8]);
            cp_async16(smem_u32(&Ks[st][plr][pc0 + 16]), &g_k[roff + 16]);
            cp_async16(smem_u32(&Ks[st][plr][pc0 + 24]), &g_k[roff + 24]);
            cp_async16(smem_u32(&Vs[st][plr][pc0]),      &g_v[roff]);
            cp_async16(smem_u32(&Vs[st][plr][pc0 + 8]),  &g_v[roff + 8]);
            cp_async16(smem_u32(&Vs[st][plr][pc0 + 16]), &g_v[roff + 16]);
            cp_async16(smem_u32(&Vs[st][plr][pc0 + 24]), &g_v[roff + 24]);
            CP_COMMIT();
            CP_WAIT(1);
        } else {
            CP_WAIT(0);
        }
        __syncthreads();
        unsigned soff = (jt & 1) * stageB;
        int j0 = jt * 64;

        // S = Q K^T  (per warp: 16 x 64), already scaled via q
        float s[8][4] = {};
        #pragma unroll
        for (int c4 = 0; c4 < 4; c4++) {
            #pragma unroll
            for (int p = 0; p < 4; p++) {
                unsigned bb[4];
                ldsm_x4(bb, ka_base + soff + (p * 16 * 72 + c4 * 16) * 2);
                mma16816(s[2 * p],     qf[c4], bb);
                mma16816(s[2 * p + 1], qf[c4], bb + 2);
            }
        }

        // BD add: warp-uniform fast paths (tile fully before/after diagonal)
        float rmax0 = -1e30f, rmax1 = -1e30f;
        bool allA  = (j0 + 63) <= (i0 + w * 16);
        bool allA1 = j0 >= (i0 + w * 16 + 17);
        if (allA | allA1) {
            float b0 = allA ? cA : cA1;
            float b1 = allA ? cB : cB1;
            #pragma unroll
            for (int nt = 0; nt < 8; nt++) {
                s[nt][0] += b0; s[nt][1] += b0;
                s[nt][2] += b1; s[nt][3] += b1;
                rmax0 = fmaxf(rmax0, fmaxf(s[nt][0], s[nt][1]));
                rmax1 = fmaxf(rmax1, fmaxf(s[nt][2], s[nt][3]));
            }
        } else {
            #pragma unroll
            for (int nt = 0; nt < 8; nt++) {
                int gj = j0 + nt * 8 + tig * 2;
                float bd00 = (gj <= r0) ? cA : ((gj == r0 + 1) ? 0.f : cA1);
                float bd01 = (gj + 1 <= r0) ? cA : ((gj + 1 == r0 + 1) ? 0.f : cA1);
                float bd10 = (gj <= r1) ? cB : ((gj == r1 + 1) ? 0.f : cB1);
                float bd11 = (gj + 1 <= r1) ? cB : ((gj + 1 == r1 + 1) ? 0.f : cB1);
                s[nt][0] += bd00; s[nt][1] += bd01;
                s[nt][2] += bd10; s[nt][3] += bd11;
                rmax0 = fmaxf(rmax0, fmaxf(s[nt][0], s[nt][1]));
                rmax1 = fmaxf(rmax1, fmaxf(s[nt][2], s[nt][3]));
            }
        }
        rmax0 = fmaxf(rmax0, __shfl_xor_sync(~0u, rmax0, 1));
        rmax0 = fmaxf(rmax0, __shfl_xor_sync(~0u, rmax0, 2));
        rmax1 = fmaxf(rmax1, __shfl_xor_sync(~0u, rmax1, 1));
        rmax1 = fmaxf(rmax1, __shfl_xor_sync(~0u, rmax1, 2));
        float mn0 = fmaxf(m0v, rmax0), mn1 = fmaxf(m1v, rmax1);
        float al0 = __expf(m0v - mn0), al1 = __expf(m1v - mn1);
        float rs0 = 0.f, rs1 = 0.f;
        unsigned ph0[8], ph1[8];
        #pragma unroll
        for (int nt = 0; nt < 8; nt++) {
            float p0 = __expf(s[nt][0] - mn0), p1 = __expf(s[nt][1] - mn0);
            float p2 = __expf(s[nt][2] - mn1), p3 = __expf(s[nt][3] - mn1);
            rs0 += p0 + p1; rs1 += p2 + p3;
            __half2 t0 = __floats2half2_rn(p0, p1);
            __half2 t1 = __floats2half2_rn(p2, p3);
            ph0[nt] = *(unsigned*)&t0;
            ph1[nt] = *(unsigned*)&t1;
        }
        rs0 += __shfl_xor_sync(~0u, rs0, 1);
        rs0 += __shfl_xor_sync(~0u, rs0, 2);
        rs1 += __shfl_xor_sync(~0u, rs1, 1);
        rs1 += __shfl_xor_sync(~0u, rs1, 2);
        l0 = l0 * al0 + rs0; l1 = l1 * al1 + rs1;
        m0v = mn0; m1v = mn1;
        #pragma unroll
        for (int nt = 0; nt < 8; nt++) {
            o[nt][0] *= al0; o[nt][1] *= al0;
            o[nt][2] *= al1; o[nt][3] *= al1;
        }

        // O += P V   (A from regs; B via ldmatrix.trans on natural V[j][d])
        #pragma unroll
        for (int c4 = 0; c4 < 4; c4++) {
            unsigned a[4] = { ph0[2 * c4], ph1[2 * c4], ph0[2 * c4 + 1], ph1[2 * c4 + 1] };
            #pragma unroll
            for (int p = 0; p < 4; p++) {
                unsigned bb[4];
                ldsm_x4_trans(bb, va_base + soff + (c4 * 16 * 72 + p * 16) * 2);
                mma16816(o[2 * p],     a, bb);
                mma16816(o[2 * p + 1], a, bb + 2);
            }
        }
        __syncthreads();
    }

    float inv0 = 1.f / l0, inv1 = 1.f / l1;
    #pragma unroll
    for (int nt = 0; nt < 8; nt++) {
        int d = nt * 8 + tig * 2;
        *(__half2*)&g_av[((size_t)r0 * kB + b) * kD + h * kDh + d] =
            __floats2half2_rn(o[nt][0] * inv0, o[nt][1] * inv0);
        *(__half2*)&g_av[((size_t)r1 * kB + b) * kD + h * kDh + d] =
            __floats2half2_rn(o[nt][2] * inv1, o[nt][3] * inv1);
    }
}

// ---------------------- Output GEMM + residual (fp16 mma) --------------------
__global__ __launch_bounds__(256) void gemm_out_kernel(float* __restrict__ out) {
    __shared__ __half As[2][128][40];
    __shared__ __half Bs[2][128][40];
    int tid = threadIdx.x, lane = tid & 31, w = tid >> 5;
    int gid = lane >> 2, tig = lane & 3;
    int m0 = blockIdx.y * 128, n0 = blockIdx.x * 128;
    int wm = w >> 2, wn = w & 3;
    constexpr unsigned stageB = 128 * 40 * 2;
    unsigned a_base = smem_u32(&As[0][wm * 64 + (lane & 15)][(lane >> 4) * 8]);
    unsigned b_base = smem_u32(&Bs[0][wn * 32 + (lane & 7) + ((lane >> 4) << 3)][((lane >> 3) & 1) * 8]);
    int lr = tid >> 2, lc = (tid & 3) * 8;
    int lr2 = lr + 64;
    float acc[4][4][4] = {};

    cp_async16(smem_u32(&As[0][lr][lc]),  &g_av[(size_t)(m0 + lr) * kD + lc]);
    cp_async16(smem_u32(&As[0][lr2][lc]), &g_av[(size_t)(m0 + lr2) * kD + lc]);
    cp_async16(smem_u32(&Bs[0][lr][lc]),  &g_wo_t[(size_t)(n0 + lr) * kD + lc]);
    cp_async16(smem_u32(&Bs[0][lr2][lc]), &g_wo_t[(size_t)(n0 + lr2) * kD + lc]);
    CP_COMMIT();

    constexpr int NIT = kD / 32;
    for (int it = 0; it < NIT; it++) {
        if (it + 1 < NIT) {
            int st = (it + 1) & 1, k0 = (it + 1) * 32;
            cp_async16(smem_u32(&As[st][lr][lc]),  &g_av[(size_t)(m0 + lr) * kD + k0 + lc]);
            cp_async16(smem_u32(&As[st][lr2][lc]), &g_av[(size_t)(m0 + lr2) * kD + k0 + lc]);
            cp_async16(smem_u32(&Bs[st][lr][lc]),  &g_wo_t[(size_t)(n0 + lr) * kD + k0 + lc]);
            cp_async16(smem_u32(&Bs[st][lr2][lc]), &g_wo_t[(size_t)(n0 + lr2) * kD + k0 + lc]);
            CP_COMMIT();
            CP_WAIT(1);
        } else {
            CP_WAIT(0);
        }
        __syncthreads();
        unsigned soff = (it & 1) * stageB;
        #pragma unroll
        for (int kb = 0; kb < 32; kb += 16) {
            unsigned a[4][4], b[2][4];
            #pragma unroll
            for (int mi = 0; mi < 4; mi++)
                ldsm_x4(a[mi], a_base + soff + (mi * 16 * 40 + kb) * 2);
            #pragma unroll
            for (int p = 0; p < 2; p++)
                ldsm_x4(b[p], b_base + soff + (p * 16 * 40 + kb) * 2);
            #pragma unroll
            for (int mi = 0; mi < 4; mi++)
                #pragma unroll
                for (int p = 0; p < 2; p++) {
                    mma16816(acc[mi][2 * p],     a[mi], b[p]);
                    mma16816(acc[mi][2 * p + 1], a[mi], b[p] + 2);
                }
        }
        __syncthreads();
    }
    #pragma unroll
    for (int mi = 0; mi < 4; mi++) {
        int r0e = m0 + wm * 64 + mi * 16 + gid, r1e = r0e + 8;
        #pragma unroll
        for (int ni = 0; ni < 4; ni++) {
            int c0 = n0 + wn * 32 + ni * 8 + tig * 2;
            float2 x0 = *(const float2*)&g_xn[(size_t)r0e * kD + c0];
            float2 x1 = *(const float2*)&g_xn[(size_t)r1e * kD + c0];
            float2 o0 = { acc[mi][ni][0] + x0.x, acc[mi][ni][1] + x0.y };
            float2 o1 = { acc[mi][ni][2] + x1.x, acc[mi][ni][3] + x1.y };
            *(float2*)&out[(size_t)r0e * kD + c0] = o0;
            *(float2*)&out[(size_t)r1e * kD + c0] = o1;
        }
    }
}

// --------------------------------- launch ------------------------------------
extern "C" void kernel_launch(void* const* d_in, const int* in_sizes, int n_in,
                              void* d_out, int out_size) {
    const float* x    = (const float*)d_in[0];
    const float* r    = (const float*)d_in[1];
    const float* rw   = (const float*)d_in[2];
    const float* rr   = (const float*)d_in[3];
    const float* ln_g = (const float*)d_in[4];
    const float* ln_b = (const float*)d_in[5];
    const float* Wqkv = (const float*)d_in[6];
    const float* Wr   = (const float*)d_in[7];
    const float* Wo   = (const float*)d_in[8];
    float* out = (float*)d_out;

    prologue_kernel<<<kNbLn + kNbCw0 + kNbCw1 + kNbRk, 256>>>(x, ln_g, ln_b, Wqkv, Wo, r, Wr);
    rk0_reduce_kernel<<<kD / 256, 256>>>();
    gemm_qkv_kernel<<<dim3(3 * kD / 128, kRows / 128), 256>>>(rw);
    flash_kernel<<<dim3(kS / 64, kH, kB), 128>>>(rw, rr);
    gemm_out_kernel<<<dim3(kD / 128, kRows / 128), 256>>>(out);
}

// round 16
// speedup vs baseline: 1.0569x; 1.0569x over previous
#include <cuda_runtime.h>
#include <cuda_fp16.h>
#include <math.h>

namespace {
constexpr int kS = 2048, kB = 2, kD = 1024, kH = 16, kDh = 64;
constexpr int kRows = kS * kB;            // 4096
constexpr float kScale = 0.125f;          // 1/sqrt(64), folded into q + BD consts
constexpr float kEps = 1e-5f;
constexpr int kRkChunks = 16;
// prologue block ranges
constexpr int kNbLn  = kRows;                       // 4096
constexpr int kNbCw0 = (3 * kD / 32) * (kD / 32);   // 3072
constexpr int kNbCw1 = (kD / 32) * (kD / 32);       // 1024
constexpr int kNbRk  = (kD / 256) * kRkChunks;      // 64
}

// ------------------------- scratch (static device memory) -------------------
// NOTE: only referenced inside device code — never passed as kernel args.
__device__ float  g_xn[kRows * kD];
__device__ __half g_xn_h[kRows * kD];
__device__ __half g_wqkv_t[3 * kD * kD];           // Wqkv^T [n][k]
__device__ __half g_wo_t[kD * kD];                 // Wo^T [n][k]
__device__ __half g_q[kB * kH * kS * kDh];         // (q + rw) * kScale  [b][h][s][d]
__device__ __half g_k[kB * kH * kS * kDh];         // [b][h][s][d]
__device__ __half g_v[kB * kH * kS * kDh];         // [b][h][s][d]
__device__ __half g_av[kRows * kD];
__device__ float  g_rk0p[kRkChunks * kD];
__device__ float  g_rk0[kD];

// ------------------------------ asm helpers ----------------------------------
__device__ __forceinline__ void mma16816(float* c, const unsigned* a, const unsigned* b) {
    asm volatile(
        "mma.sync.aligned.m16n8k16.row.col.f32.f16.f16.f32 "
        "{%0,%1,%2,%3},{%4,%5,%6,%7},{%8,%9},{%0,%1,%2,%3};\n"
        : "+f"(c[0]), "+f"(c[1]), "+f"(c[2]), "+f"(c[3])
        : "r"(a[0]), "r"(a[1]), "r"(a[2]), "r"(a[3]), "r"(b[0]), "r"(b[1]));
}
__device__ __forceinline__ void ldsm_x4(unsigned* r, unsigned addr) {
    asm volatile("ldmatrix.sync.aligned.m8n8.x4.shared.b16 {%0,%1,%2,%3}, [%4];\n"
                 : "=r"(r[0]), "=r"(r[1]), "=r"(r[2]), "=r"(r[3]) : "r"(addr));
}
__device__ __forceinline__ void ldsm_x4_trans(unsigned* r, unsigned addr) {
    asm volatile("ldmatrix.sync.aligned.m8n8.x4.trans.shared.b16 {%0,%1,%2,%3}, [%4];\n"
                 : "=r"(r[0]), "=r"(r[1]), "=r"(r[2]), "=r"(r[3]) : "r"(addr));
}
__device__ __forceinline__ unsigned smem_u32(const void* p) {
    return (unsigned)__cvta_generic_to_shared(p);
}
__device__ __forceinline__ void cp_async16(unsigned dst, const void* src) {
    asm volatile("cp.async.cg.shared.global [%0], [%1], 16;\n"
                 :: "r"(dst), "l"(__cvta_generic_to_global(src)));
}
#define CP_COMMIT() asm volatile("cp.async.commit_group;\n")
#define CP_WAIT(n)  asm volatile("cp.async.wait_group %0;\n" :: "n"(n))

// ------------------- fused prologue: ln | convw0 | convw1 | rk0_part ---------
__global__ __launch_bounds__(256) void prologue_kernel(
        const float* __restrict__ x, const float* __restrict__ gamma,
        const float* __restrict__ beta, const float* __restrict__ Wqkv,
        const float* __restrict__ Wo, const float* __restrict__ r,
        const float* __restrict__ Wr) {
    __shared__ float tile[32][33];
    __shared__ float sm1[8], sm2[8];
    int blk = blockIdx.x;
    int tid = threadIdx.x;

    if (blk < kNbLn) {
        // ---------------- LayerNorm ----------------
        int row = blk, t = tid;
        const float4 v = reinterpret_cast<const float4*>(x + (size_t)row * kD)[t];
        float s1 = v.x + v.y + v.z + v.w;
        float s2 = v.x*v.x + v.y*v.y + v.z*v.z + v.w*v.w;
        #pragma unroll
        for (int o = 16; o; o >>= 1) {
            s1 += __shfl_xor_sync(~0u, s1, o);
            s2 += __shfl_xor_sync(~0u, s2, o);
        }
        int w = t >> 5, lane = t & 31;
        if (lane == 0) { sm1[w] = s1; sm2[w] = s2; }
        __syncthreads();
        if (w == 0) {
            s1 = (lane < 8) ? sm1[lane] : 0.f;
            s2 = (lane < 8) ? sm2[lane] : 0.f;
            #pragma unroll
            for (int o = 4; o; o >>= 1) {
                s1 += __shfl_xor_sync(~0u, s1, o);
                s2 += __shfl_xor_sync(~0u, s2, o);
            }
            if (lane == 0) { sm1[0] = s1; sm2[0] = s2; }
        }
        __syncthreads();
        float mu = sm1[0] * (1.f / kD);
        float var = sm2[0] * (1.f / kD) - mu * mu;
        float rstd = rsqrtf(var + kEps);
        const float4 gv = reinterpret_cast<const float4*>(gamma)[t];
        const float4 bv = reinterpret_cast<const float4*>(beta)[t];
        float4 o;
        o.x = (v.x - mu) * rstd * gv.x + bv.x;
        o.y = (v.y - mu) * rstd * gv.y + bv.y;
        o.z = (v.z - mu) * rstd * gv.z + bv.z;
        o.w = (v.w - mu) * rstd * gv.w + bv.w;
        reinterpret_cast<float4*>(g_xn + (size_t)row * kD)[t] = o;
        *reinterpret_cast<__half2*>(&g_xn_h[(size_t)row * kD + t * 4])     = __floats2half2_rn(o.x, o.y);
        *reinterpret_cast<__half2*>(&g_xn_h[(size_t)row * kD + t * 4 + 2]) = __floats2half2_rn(o.z, o.w);
    } else if (blk < kNbLn + kNbCw0 + kNbCw1) {
        // ---------------- weight transpose + cast ----------------
        bool first = (blk < kNbLn + kNbCw0);
        int local = first ? (blk - kNbLn) : (blk - kNbLn - kNbCw0);
        int N = first ? 3 * kD : kD;
        const float* src = first ? Wqkv : Wo;
        __half* dst = first ? g_wqkv_t : g_wo_t;
        int nt = N / 32;
        int bx = local % nt, by = local / nt;
        int n0 = bx * 32, k0 = by * 32;
        int tx = tid & 31, ty = tid >> 5;
        #pragma unroll
        for (int i = 0; i < 32; i += 8)
            tile[ty + i][tx] = src[(size_t)(k0 + ty + i) * N + n0 + tx];
        __syncthreads();
        #pragma unroll
        for (int i = 0; i < 32; i += 8)
            dst[(size_t)(n0 + ty + i) * kD + k0 + tx] = __float2half(tile[tx][ty + i]);
    } else {
        // ---------------- rk0 partial ----------------
        int local = blk - (kNbLn + kNbCw0 + kNbCw1);
        int chunk = local >> 2, colblk = local & 3;
        int col = colblk * 256 + tid;
        int d0 = chunk * (kD / kRkChunks);
        float s = 0.f;
        #pragma unroll
        for (int i = 0; i < kD / kRkChunks; i++)
            s += r[d0 + i] * Wr[(size_t)(d0 + i) * kD + col];
        g_rk0p[chunk * kD + col] = s;
    }
}

__global__ void rk0_reduce_kernel() {
    int col = blockIdx.x * 256 + threadIdx.x;
    float s = 0.f;
    #pragma unroll
    for (int c = 0; c < kRkChunks; c++) s += g_rk0p[c * kD + col];
    g_rk0[col] = s;
}

// ------------------------------ QKV GEMM (fp16 mma, cp.async + ldmatrix) -----
__global__ __launch_bounds__(256) void gemm_qkv_kernel(const float* __restrict__ rw) {
    __shared__ __half As[2][128][40];
    __shared__ __half Bs[2][128][40];
    int tid = threadIdx.x, lane = tid & 31, w = tid >> 5;
    int gid = lane >> 2, tig = lane & 3;
    int m0 = blockIdx.y * 128, n0 = blockIdx.x * 128;
    int wm = w >> 2, wn = w & 3;
    constexpr unsigned stageB = 128 * 40 * 2;
    unsigned a_base = smem_u32(&As[0][wm * 64 + (lane & 15)][(lane >> 4) * 8]);
    unsigned b_base = smem_u32(&Bs[0][wn * 32 + (lane & 7) + ((lane >> 4) << 3)][((lane >> 3) & 1) * 8]);
    int lr = tid >> 2, lc = (tid & 3) * 8;
    int lr2 = lr + 64;
    float acc[4][4][4] = {};

    cp_async16(smem_u32(&As[0][lr][lc]),  &g_xn_h[(size_t)(m0 + lr) * kD + lc]);
    cp_async16(smem_u32(&As[0][lr2][lc]), &g_xn_h[(size_t)(m0 + lr2) * kD + lc]);
    cp_async16(smem_u32(&Bs[0][lr][lc]),  &g_wqkv_t[(size_t)(n0 + lr) * kD + lc]);
    cp_async16(smem_u32(&Bs[0][lr2][lc]), &g_wqkv_t[(size_t)(n0 + lr2) * kD + lc]);
    CP_COMMIT();

    constexpr int NIT = kD / 32;
    for (int it = 0; it < NIT; it++) {
        if (it + 1 < NIT) {
            int st = (it + 1) & 1, k0 = (it + 1) * 32;
            cp_async16(smem_u32(&As[st][lr][lc]),  &g_xn_h[(size_t)(m0 + lr) * kD + k0 + lc]);
            cp_async16(smem_u32(&As[st][lr2][lc]), &g_xn_h[(size_t)(m0 + lr2) * kD + k0 + lc]);
            cp_async16(smem_u32(&Bs[st][lr][lc]),  &g_wqkv_t[(size_t)(n0 + lr) * kD + k0 + lc]);
            cp_async16(smem_u32(&Bs[st][lr2][lc]), &g_wqkv_t[(size_t)(n0 + lr2) * kD + k0 + lc]);
            CP_COMMIT();
            CP_WAIT(1);
        } else {
            CP_WAIT(0);
        }
        __syncthreads();
        unsigned soff = (it & 1) * stageB;
        #pragma unroll
        for (int kb = 0; kb < 32; kb += 16) {
            unsigned a[4][4], b[2][4];
            #pragma unroll
            for (int mi = 0; mi < 4; mi++)
                ldsm_x4(a[mi], a_base + soff + (mi * 16 * 40 + kb) * 2);
            #pragma unroll
            for (int p = 0; p < 2; p++)
                ldsm_x4(b[p], b_base + soff + (p * 16 * 40 + kb) * 2);
            #pragma unroll
            for (int mi = 0; mi < 4; mi++)
                #pragma unroll
                for (int p = 0; p < 2; p++) {
                    mma16816(acc[mi][2 * p],     a[mi], b[p]);
                    mma16816(acc[mi][2 * p + 1], a[mi], b[p] + 2);
                }
        }
        __syncthreads();
    }
    // epilogue: scatter to q(+rw, *kScale)/k/v (all coalesced __half2)
    #pragma unroll
    for (int mi = 0; mi < 4; mi++) {
        int r0e = m0 + wm * 64 + mi * 16 + gid, r1e = r0e + 8;
        int s0 = r0e >> 1, b0e = r0e & 1;
        int s1 = r1e >> 1, b1e = r1e & 1;
        #pragma unroll
        for (int ni = 0; ni < 4; ni++) {
            int c0 = n0 + wn * 32 + ni * 8 + tig * 2;
            int part = c0 >> 10, rem = c0 & 1023, hh = rem >> 6, d = rem & 63;
            size_t di0 = (((size_t)(b0e * kH + hh)) * kS + s0) * kDh + d;
            size_t di1 = (((size_t)(b1e * kH + hh)) * kS + s1) * kDh + d;
            float v00 = acc[mi][ni][0], v01 = acc[mi][ni][1];
            float v10 = acc[mi][ni][2], v11 = acc[mi][ni][3];
            if (part == 0) {
                float w0 = rw[rem], w1 = rw[rem + 1];
                *(__half2*)&g_q[di0] =
                    __floats2half2_rn((v00 + w0) * kScale, (v01 + w1) * kScale);
                *(__half2*)&g_q[di1] =
                    __floats2half2_rn((v10 + w0) * kScale, (v11 + w1) * kScale);
            } else if (part == 1) {
                *(__half2*)&g_k[di0] = __floats2half2_rn(v00, v01);
                *(__half2*)&g_k[di1] = __floats2half2_rn(v10, v11);
            } else {
                *(__half2*)&g_v[di0] = __floats2half2_rn(v00, v01);
                *(__half2*)&g_v[di1] = __floats2half2_rn(v10, v11);
            }
        }
    }
}

// ------------- Flash attention (fp16 mma, 128q/8warp, reg-Q/P, fused cbd) ----
// Block: 256 thr = 8 warps, one (b,h), 128 query rows (16/warp), key tiles 64.
// q is pre-scaled by kScale, so S and BD constants need no further scaling.
__global__ __launch_bounds__(256) void flash_kernel(const float* __restrict__ rw,
                                                    const float* __restrict__ rr) {
    __shared__ __half Ks[2][64][72];
    __shared__ __half Vs[2][64][72];       // natural [j][d]
    __shared__ float csm[132];             // [0..128]=row dots (scaled), [130]=C_h
    int b = blockIdx.z, h = blockIdx.y, i0 = blockIdx.x * 128;
    int tid = threadIdx.x, w = tid >> 5, lane = tid & 31;
    int gid = lane >> 2, tig = lane & 3;
    size_t base = ((size_t)(b * kH + h)) * kS * kDh;

    // ---- stage Q through the K buffer (128 rows x 72 stride), capture -------
    __half* qstage = &Ks[0][0][0];
    #pragma unroll
    for (int t = 0; t < 4; t++) {
        int idx = tid + t * 256;
        int r = idx >> 3, c = (idx & 7) * 8;
        *(float4*)&qstage[r * 72 + c] = *(const float4*)&g_q[base + (size_t)(i0 + r) * kDh + c];
    }
    __syncthreads();
    unsigned qf[4][4];
    {
        unsigned qa = smem_u32(qstage + (w * 16 + (lane & 15)) * 72 + (lane >> 4) * 8);
        #pragma unroll
        for (int c4 = 0; c4 < 4; c4++) ldsm_x4(qf[c4], qa + c4 * 32);
    }
    // C_h = kScale * sum_d (rr - rw) * rk0   (warp 0)
    if (w == 0) {
        int hd = h * kDh + lane;
        float chs = (rr[hd] - rw[hd]) * g_rk0[hd]
                  + (rr[hd + 32] - rw[hd + 32]) * g_rk0[hd + 32];
        #pragma unroll
        for (int o = 16; o; o >>= 1) chs += __shfl_xor_sync(~0u, chs, o);
        if (lane == 0) csm[130] = chs * kScale;
    }
    // row dots: csm[r] = q_scaled_row . rk0  (pairs of threads per row)
    {
        int rrow = tid >> 1, halfsel = (tid & 1) * 32;
        const __half* qr = qstage + rrow * 72 + halfsel;
        const float* rk = g_rk0 + h * kDh + halfsel;
        float p = 0.f;
        #pragma unroll
        for (int d = 0; d < 32; d++) p += __half2float(qr[d]) * rk[d];
        p += __shfl_xor_sync(~0u, p, 1);
        if ((tid & 1) == 0) csm[rrow] = p;
    }
    // boundary row i0+128 (from gmem, already scaled)
    if (tid < 2) {
        int gi = i0 + 128;
        float p = 0.f;
        if (gi < kS) {
            const __half* qr = &g_q[base + (size_t)gi * kDh + tid * 32];
            const float* rk = g_rk0 + h * kDh + tid * 32;
            #pragma unroll
            for (int d = 0; d < 32; d++) p += __half2float(qr[d]) * rk[d];
        }
        p += __shfl_xor_sync(0x3u, p, 1);
        if (tid == 0) csm[128] = p;
    }
    __syncthreads();   // Q captured + csm ready; K buffer reusable

    float Ch = csm[130];
    int lr0 = w * 16 + gid;
    int r0 = i0 + lr0, r1 = r0 + 8;
    float cA  = csm[lr0] + Ch;
    float cA1 = (r0 + 1 < kS) ? csm[lr0 + 1] + Ch : 0.f;
    float cB  = csm[lr0 + 8] + Ch;
    float cB1 = (r1 + 1 < kS) ? csm[lr0 + 9] + Ch : 0.f;

    unsigned ka_base = smem_u32(&Ks[0][(lane & 7) + ((lane >> 4) << 3)][((lane >> 3) & 1) * 8]);
    unsigned va_base = smem_u32(&Vs[0][(lane & 7) + (((lane >> 3) & 1) << 3)][(lane >> 4) * 8]);
    constexpr unsigned stageB = 64 * 72 * 2;

    float m0v = -1e30f, m1v = -1e30f, l0 = 0.f, l1 = 0.f;
    float o[8][4] = {};

    // pipeline loader: 64 rows x 64 halfs = 512 chunks/array; 256 thr x 2 chunks
    int plr = tid >> 2, plc = (tid & 3) * 8;
    cp_async16(smem_u32(&Ks[0][plr][plc]),      &g_k[base + (size_t)plr * kDh + plc]);
    cp_async16(smem_u32(&Ks[0][plr][plc + 32]), &g_k[base + (size_t)plr * kDh + plc + 32]);
    cp_async16(smem_u32(&Vs[0][plr][plc]),      &g_v[base + (size_t)plr * kDh + plc]);
    cp_async16(smem_u32(&Vs[0][plr][plc + 32]), &g_v[base + (size_t)plr * kDh + plc + 32]);
    CP_COMMIT();

    constexpr int NT = kS / 64;
    for (int jt = 0; jt < NT; jt++) {
        if (jt + 1 < NT) {
            int st = (jt + 1) & 1;
            size_t roff = base + (size_t)((jt + 1) * 64 + plr) * kDh + plc;
            cp_async16(smem_u32(&Ks[st][plr][plc]),      &g_k[roff]);
            cp_async16(smem_u32(&Ks[st][plr][plc + 32]), &g_k[roff + 32]);
            cp_async16(smem_u32(&Vs[st][plr][plc]),      &g_v[roff]);
            cp_async16(smem_u32(&Vs[st][plr][plc + 32]), &g_v[roff + 32]);
            CP_COMMIT();
            CP_WAIT(1);
        } else {
            CP_WAIT(0);
        }
        __syncthreads();
        unsigned soff = (jt & 1) * stageB;
        int j0 = jt * 64;

        // S = Q K^T  (per warp: 16 x 64), already scaled via q
        float s[8][4] = {};
        #pragma unroll
        for (int c4 = 0; c4 < 4; c4++) {
            #pragma unroll
            for (int p = 0; p < 4; p++) {
                unsigned bb[4];
                ldsm_x4(bb, ka_base + soff + (p * 16 * 72 + c4 * 16) * 2);
                mma16816(s[2 * p],     qf[c4], bb);
                mma16816(s[2 * p + 1], qf[c4], bb + 2);
            }
        }

        // BD add: warp-uniform fast paths (tile fully before/after diagonal)
        float rmax0 = -1e30f, rmax1 = -1e30f;
        bool allA  = (j0 + 63) <= (i0 + w * 16);
        bool allA1 = j0 >= (i0 + w * 16 + 17);
        if (allA | allA1) {
            float b0 = allA ? cA : cA1;
            float b1 = allA ? cB : cB1;
            #pragma unroll
            for (int nt = 0; nt < 8; nt++) {
                s[nt][0] += b0; s[nt][1] += b0;
                s[nt][2] += b1; s[nt][3] += b1;
                rmax0 = fmaxf(rmax0, fmaxf(s[nt][0], s[nt][1]));
                rmax1 = fmaxf(rmax1, fmaxf(s[nt][2], s[nt][3]));
            }
        } else {
            #pragma unroll
            for (int nt = 0; nt < 8; nt++) {
                int gj = j0 + nt * 8 + tig * 2;
                float bd00 = (gj <= r0) ? cA : ((gj == r0 + 1) ? 0.f : cA1);
                float bd01 = (gj + 1 <= r0) ? cA : ((gj + 1 == r0 + 1) ? 0.f : cA1);
                float bd10 = (gj <= r1) ? cB : ((gj == r1 + 1) ? 0.f : cB1);
                float bd11 = (gj + 1 <= r1) ? cB : ((gj + 1 == r1 + 1) ? 0.f : cB1);
                s[nt][0] += bd00; s[nt][1] += bd01;
                s[nt][2] += bd10; s[nt][3] += bd11;
                rmax0 = fmaxf(rmax0, fmaxf(s[nt][0], s[nt][1]));
                rmax1 = fmaxf(rmax1, fmaxf(s[nt][2], s[nt][3]));
            }
        }
        rmax0 = fmaxf(rmax0, __shfl_xor_sync(~0u, rmax0, 1));
        rmax0 = fmaxf(rmax0, __shfl_xor_sync(~0u, rmax0, 2));
        rmax1 = fmaxf(rmax1, __shfl_xor_sync(~0u, rmax1, 1));
        rmax1 = fmaxf(rmax1, __shfl_xor_sync(~0u, rmax1, 2));
        float mn0 = fmaxf(m0v, rmax0), mn1 = fmaxf(m1v, rmax1);
        float al0 = __expf(m0v - mn0), al1 = __expf(m1v - mn1);
        float rs0 = 0.f, rs1 = 0.f;
        unsigned ph0[8], ph1[8];
        #pragma unroll
        for (int nt = 0; nt < 8; nt++) {
            float p0 = __expf(s[nt][0] - mn0), p1 = __expf(s[nt][1] - mn0);
            float p2 = __expf(s[nt][2] - mn1), p3 = __expf(s[nt][3] - mn1);
            rs0 += p0 + p1; rs1 += p2 + p3;
            __half2 t0 = __floats2half2_rn(p0, p1);
            __half2 t1 = __floats2half2_rn(p2, p3);
            ph0[nt] = *(unsigned*)&t0;
            ph1[nt] = *(unsigned*)&t1;
        }
        rs0 += __shfl_xor_sync(~0u, rs0, 1);
        rs0 += __shfl_xor_sync(~0u, rs0, 2);
        rs1 += __shfl_xor_sync(~0u, rs1, 1);
        rs1 += __shfl_xor_sync(~0u, rs1, 2);
        l0 = l0 * al0 + rs0; l1 = l1 * al1 + rs1;
        m0v = mn0; m1v = mn1;
        #pragma unroll
        for (int nt = 0; nt < 8; nt++) {
            o[nt][0] *= al0; o[nt][1] *= al0;
            o[nt][2] *= al1; o[nt][3] *= al1;
        }

        // O += P V   (A from regs; B via ldmatrix.trans on natural V[j][d])
        #pragma unroll
        for (int c4 = 0; c4 < 4; c4++) {
            unsigned a[4] = { ph0[2 * c4], ph1[2 * c4], ph0[2 * c4 + 1], ph1[2 * c4 + 1] };
            #pragma unroll
            for (int p = 0; p < 4; p++) {
                unsigned bb[4];
                ldsm_x4_trans(bb, va_base + soff + (c4 * 16 * 72 + p * 16) * 2);
                mma16816(o[2 * p],     a, bb);
                mma16816(o[2 * p + 1], a, bb + 2);
            }
        }
        __syncthreads();
    }

    float inv0 = 1.f / l0, inv1 = 1.f / l1;
    #pragma unroll
    for (int nt = 0; nt < 8; nt++) {
        int d = nt * 8 + tig * 2;
        *(__half2*)&g_av[((size_t)r0 * kB + b) * kD + h * kDh + d] =
            __floats2half2_rn(o[nt][0] * inv0, o[nt][1] * inv0);
        *(__half2*)&g_av[((size_t)r1 * kB + b) * kD + h * kDh + d] =
            __floats2half2_rn(o[nt][2] * inv1, o[nt][3] * inv1);
    }
}

// ---------------------- Output GEMM + residual (fp16 mma) --------------------
__global__ __launch_bounds__(256) void gemm_out_kernel(float* __restrict__ out) {
    __shared__ __half As[2][128][40];
    __shared__ __half Bs[2][128][40];
    int tid = threadIdx.x, lane = tid & 31, w = tid >> 5;
    int gid = lane >> 2, tig = lane & 3;
    int m0 = blockIdx.y * 128, n0 = blockIdx.x * 128;
    int wm = w >> 2, wn = w & 3;
    constexpr unsigned stageB = 128 * 40 * 2;
    unsigned a_base = smem_u32(&As[0][wm * 64 + (lane & 15)][(lane >> 4) * 8]);
    unsigned b_base = smem_u32(&Bs[0][wn * 32 + (lane & 7) + ((lane >> 4) << 3)][((lane >> 3) & 1) * 8]);
    int lr = tid >> 2, lc = (tid & 3) * 8;
    int lr2 = lr + 64;
    float acc[4][4][4] = {};

    cp_async16(smem_u32(&As[0][lr][lc]),  &g_av[(size_t)(m0 + lr) * kD + lc]);
    cp_async16(smem_u32(&As[0][lr2][lc]), &g_av[(size_t)(m0 + lr2) * kD + lc]);
    cp_async16(smem_u32(&Bs[0][lr][lc]),  &g_wo_t[(size_t)(n0 + lr) * kD + lc]);
    cp_async16(smem_u32(&Bs[0][lr2][lc]), &g_wo_t[(size_t)(n0 + lr2) * kD + lc]);
    CP_COMMIT();

    constexpr int NIT = kD / 32;
    for (int it = 0; it < NIT; it++) {
        if (it + 1 < NIT) {
            int st = (it + 1) & 1, k0 = (it + 1) * 32;
            cp_async16(smem_u32(&As[st][lr][lc]),  &g_av[(size_t)(m0 + lr) * kD + k0 + lc]);
            cp_async16(smem_u32(&As[st][lr2][lc]), &g_av[(size_t)(m0 + lr2) * kD + k0 + lc]);
            cp_async16(smem_u32(&Bs[st][lr][lc]),  &g_wo_t[(size_t)(n0 + lr) * kD + k0 + lc]);
            cp_async16(smem_u32(&Bs[st][lr2][lc]), &g_wo_t[(size_t)(n0 + lr2) * kD + k0 + lc]);
            CP_COMMIT();
            CP_WAIT(1);
        } else {
            CP_WAIT(0);
        }
        __syncthreads();
        unsigned soff = (it & 1) * stageB;
        #pragma unroll
        for (int kb = 0; kb < 32; kb += 16) {
            unsigned a[4][4], b[2][4];
            #pragma unroll
            for (int mi = 0; mi < 4; mi++)
                ldsm_x4(a[mi], a_base + soff + (mi * 16 * 40 + kb) * 2);
            #pragma unroll
            for (int p = 0; p < 2; p++)
                ldsm_x4(b[p], b_base + soff + (p * 16 * 40 + kb) * 2);
            #pragma unroll
            for (int mi = 0; mi < 4; mi++)
                #pragma unroll
                for (int p = 0; p < 2; p++) {
                    mma16816(acc[mi][2 * p],     a[mi], b[p]);
                    mma16816(acc[mi][2 * p + 1], a[mi], b[p] + 2);
                }
        }
        __syncthreads();
    }
    #pragma unroll
    for (int mi = 0; mi < 4; mi++) {
        int r0e = m0 + wm * 64 + mi * 16 + gid, r1e = r0e + 8;
        #pragma unroll
        for (int ni = 0; ni < 4; ni++) {
            int c0 = n0 + wn * 32 + ni * 8 + tig * 2;
            float2 x0 = *(const float2*)&g_xn[(size_t)r0e * kD + c0];
            float2 x1 = *(const float2*)&g_xn[(size_t)r1e * kD + c0];
            float2 o0 = { acc[mi][ni][0] + x0.x, acc[mi][ni][1] + x0.y };
            float2 o1 = { acc[mi][ni][2] + x1.x, acc[mi][ni][3] + x1.y };
            *(float2*)&out[(size_t)r0e * kD + c0] = o0;
            *(float2*)&out[(size_t)r1e * kD + c0] = o1;
        }
    }
}

// --------------------------------- launch ------------------------------------
extern "C" void kernel_launch(void* const* d_in, const int* in_sizes, int n_in,
                              void* d_out, int out_size) {
    const float* x    = (const float*)d_in[0];
    const float* r    = (const float*)d_in[1];
    const float* rw   = (const float*)d_in[2];
    const float* rr   = (const float*)d_in[3];
    const float* ln_g = (const float*)d_in[4];
    const float* ln_b = (const float*)d_in[5];
    const float* Wqkv = (const float*)d_in[6];
    const float* Wr   = (const float*)d_in[7];
    const float* Wo   = (const float*)d_in[8];
    float* out = (float*)d_out;

    prologue_kernel<<<kNbLn + kNbCw0 + kNbCw1 + kNbRk, 256>>>(x, ln_g, ln_b, Wqkv, Wo, r, Wr);
    rk0_reduce_kernel<<<kD / 256, 256>>>();
    gemm_qkv_kernel<<<dim3(3 * kD / 128, kRows / 128), 256>>>(rw);
    flash_kernel<<<dim3(kS / 128, kH, kB), 256>>>(rw, rr);
    gemm_out_kernel<<<dim3(kD / 128, kRows / 128), 256>>>(out);
}

// round 17
// speedup vs baseline: 1.0970x; 1.0379x over previous
#include <cuda_runtime.h>
#include <cuda_fp16.h>
#include <math.h>

namespace {
constexpr int kS = 2048, kB = 2, kD = 1024, kH = 16, kDh = 64;
constexpr int kRows = kS * kB;            // 4096
constexpr float kQScale = 0.125f * 1.44269504089f;  // kScale * log2(e), folded into q
constexpr float kEps = 1e-5f;
constexpr int kRkChunks = 16;
// prologue block ranges
constexpr int kNbLn  = kRows;                       // 4096
constexpr int kNbCw0 = (3 * kD / 32) * (kD / 32);   // 3072
constexpr int kNbCw1 = (kD / 32) * (kD / 32);       // 1024
constexpr int kNbRk  = (kD / 256) * kRkChunks;      // 64
}

// ------------------------- scratch (static device memory) -------------------
// NOTE: only referenced inside device code — never passed as kernel args.
__device__ float  g_xn[kRows * kD];
__device__ __half g_xn_h[kRows * kD];
__device__ __half g_wqkv_t[3 * kD * kD];           // Wqkv^T [n][k]
__device__ __half g_wo_t[kD * kD];                 // Wo^T [n][k]
__device__ __half g_q[kB * kH * kS * kDh];         // (q + rw) * kQScale  [b][h][s][d]
__device__ __half g_k[kB * kH * kS * kDh];         // [b][h][s][d]
__device__ __half g_v[kB * kH * kS * kDh];         // [b][h][s][d]
__device__ __half g_av[kRows * kD];
__device__ float  g_rk0p[kRkChunks * kD];
__device__ float  g_rk0[kD];

// ------------------------------ asm helpers ----------------------------------
__device__ __forceinline__ void mma16816(float* c, const unsigned* a, const unsigned* b) {
    asm volatile(
        "mma.sync.aligned.m16n8k16.row.col.f32.f16.f16.f32 "
        "{%0,%1,%2,%3},{%4,%5,%6,%7},{%8,%9},{%0,%1,%2,%3};\n"
        : "+f"(c[0]), "+f"(c[1]), "+f"(c[2]), "+f"(c[3])
        : "r"(a[0]), "r"(a[1]), "r"(a[2]), "r"(a[3]), "r"(b[0]), "r"(b[1]));
}
__device__ __forceinline__ void ldsm_x4(unsigned* r, unsigned addr) {
    asm volatile("ldmatrix.sync.aligned.m8n8.x4.shared.b16 {%0,%1,%2,%3}, [%4];\n"
                 : "=r"(r[0]), "=r"(r[1]), "=r"(r[2]), "=r"(r[3]) : "r"(addr));
}
__device__ __forceinline__ void ldsm_x4_trans(unsigned* r, unsigned addr) {
    asm volatile("ldmatrix.sync.aligned.m8n8.x4.trans.shared.b16 {%0,%1,%2,%3}, [%4];\n"
                 : "=r"(r[0]), "=r"(r[1]), "=r"(r[2]), "=r"(r[3]) : "r"(addr));
}
__device__ __forceinline__ unsigned smem_u32(const void* p) {
    return (unsigned)__cvta_generic_to_shared(p);
}
__device__ __forceinline__ void cp_async16(unsigned dst, const void* src) {
    asm volatile("cp.async.cg.shared.global [%0], [%1], 16;\n"
                 :: "r"(dst), "l"(__cvta_generic_to_global(src)));
}
#define CP_COMMIT() asm volatile("cp.async.commit_group;\n")
#define CP_WAIT(n)  asm volatile("cp.async.wait_group %0;\n" :: "n"(n))
__device__ __forceinline__ unsigned h2ex2(unsigned x) {
    unsigned d;
    asm("ex2.approx.f16x2 %0, %1;" : "=r"(d) : "r"(x));
    return d;
}
__device__ __forceinline__ float fex2(float x) {
    float d;
    asm("ex2.approx.f32 %0, %1;" : "=f"(d) : "f"(x));
    return d;
}

// ------------------- fused prologue: ln | convw0 | convw1 | rk0_part ---------
__global__ __launch_bounds__(256) void prologue_kernel(
        const float* __restrict__ x, const float* __restrict__ gamma,
        const float* __restrict__ beta, const float* __restrict__ Wqkv,
        const float* __restrict__ Wo, const float* __restrict__ r,
        const float* __restrict__ Wr) {
    __shared__ float tile[32][33];
    __shared__ float sm1[8], sm2[8];
    int blk = blockIdx.x;
    int tid = threadIdx.x;

    if (blk < kNbLn) {
        // ---------------- LayerNorm ----------------
        int row = blk, t = tid;
        const float4 v = reinterpret_cast<const float4*>(x + (size_t)row * kD)[t];
        float s1 = v.x + v.y + v.z + v.w;
        float s2 = v.x*v.x + v.y*v.y + v.z*v.z + v.w*v.w;
        #pragma unroll
        for (int o = 16; o; o >>= 1) {
            s1 += __shfl_xor_sync(~0u, s1, o);
            s2 += __shfl_xor_sync(~0u, s2, o);
        }
        int w = t >> 5, lane = t & 31;
        if (lane == 0) { sm1[w] = s1; sm2[w] = s2; }
        __syncthreads();
        if (w == 0) {
            s1 = (lane < 8) ? sm1[lane] : 0.f;
            s2 = (lane < 8) ? sm2[lane] : 0.f;
            #pragma unroll
            for (int o = 4; o; o >>= 1) {
                s1 += __shfl_xor_sync(~0u, s1, o);
                s2 += __shfl_xor_sync(~0u, s2, o);
            }
            if (lane == 0) { sm1[0] = s1; sm2[0] = s2; }
        }
        __syncthreads();
        float mu = sm1[0] * (1.f / kD);
        float var = sm2[0] * (1.f / kD) - mu * mu;
        float rstd = rsqrtf(var + kEps);
        const float4 gv = reinterpret_cast<const float4*>(gamma)[t];
        const float4 bv = reinterpret_cast<const float4*>(beta)[t];
        float4 o;
        o.x = (v.x - mu) * rstd * gv.x + bv.x;
        o.y = (v.y - mu) * rstd * gv.y + bv.y;
        o.z = (v.z - mu) * rstd * gv.z + bv.z;
        o.w = (v.w - mu) * rstd * gv.w + bv.w;
        reinterpret_cast<float4*>(g_xn + (size_t)row * kD)[t] = o;
        *reinterpret_cast<__half2*>(&g_xn_h[(size_t)row * kD + t * 4])     = __floats2half2_rn(o.x, o.y);
        *reinterpret_cast<__half2*>(&g_xn_h[(size_t)row * kD + t * 4 + 2]) = __floats2half2_rn(o.z, o.w);
    } else if (blk < kNbLn + kNbCw0 + kNbCw1) {
        // ---------------- weight transpose + cast ----------------
        bool first = (blk < kNbLn + kNbCw0);
        int local = first ? (blk - kNbLn) : (blk - kNbLn - kNbCw0);
        int N = first ? 3 * kD : kD;
        const float* src = first ? Wqkv : Wo;
        __half* dst = first ? g_wqkv_t : g_wo_t;
        int nt = N / 32;
        int bx = local % nt, by = local / nt;
        int n0 = bx * 32, k0 = by * 32;
        int tx = tid & 31, ty = tid >> 5;
        #pragma unroll
        for (int i = 0; i < 32; i += 8)
            tile[ty + i][tx] = src[(size_t)(k0 + ty + i) * N + n0 + tx];
        __syncthreads();
        #pragma unroll
        for (int i = 0; i < 32; i += 8)
            dst[(size_t)(n0 + ty + i) * kD + k0 + tx] = __float2half(tile[tx][ty + i]);
    } else {
        // ---------------- rk0 partial ----------------
        int local = blk - (kNbLn + kNbCw0 + kNbCw1);
        int chunk = local >> 2, colblk = local & 3;
        int col = colblk * 256 + tid;
        int d0 = chunk * (kD / kRkChunks);
        float s = 0.f;
        #pragma unroll
        for (int i = 0; i < kD / kRkChunks; i++)
            s += r[d0 + i] * Wr[(size_t)(d0 + i) * kD + col];
        g_rk0p[chunk * kD + col] = s;
    }
}

__global__ void rk0_reduce_kernel() {
    int col = blockIdx.x * 256 + threadIdx.x;
    float s = 0.f;
    #pragma unroll
    for (int c = 0; c < kRkChunks; c++) s += g_rk0p[c * kD + col];
    g_rk0[col] = s;
}

// ------------------------------ QKV GEMM (fp16 mma, cp.async + ldmatrix) -----
__global__ __launch_bounds__(256) void gemm_qkv_kernel(const float* __restrict__ rw) {
    __shared__ __half As[2][128][40];
    __shared__ __half Bs[2][128][40];
    int tid = threadIdx.x, lane = tid & 31, w = tid >> 5;
    int gid = lane >> 2, tig = lane & 3;
    int m0 = blockIdx.y * 128, n0 = blockIdx.x * 128;
    int wm = w >> 2, wn = w & 3;
    constexpr unsigned stageB = 128 * 40 * 2;
    unsigned a_base = smem_u32(&As[0][wm * 64 + (lane & 15)][(lane >> 4) * 8]);
    unsigned b_base = smem_u32(&Bs[0][wn * 32 + (lane & 7) + ((lane >> 4) << 3)][((lane >> 3) & 1) * 8]);
    int lr = tid >> 2, lc = (tid & 3) * 8;
    int lr2 = lr + 64;
    float acc[4][4][4] = {};

    cp_async16(smem_u32(&As[0][lr][lc]),  &g_xn_h[(size_t)(m0 + lr) * kD + lc]);
    cp_async16(smem_u32(&As[0][lr2][lc]), &g_xn_h[(size_t)(m0 + lr2) * kD + lc]);
    cp_async16(smem_u32(&Bs[0][lr][lc]),  &g_wqkv_t[(size_t)(n0 + lr) * kD + lc]);
    cp_async16(smem_u32(&Bs[0][lr2][lc]), &g_wqkv_t[(size_t)(n0 + lr2) * kD + lc]);
    CP_COMMIT();

    constexpr int NIT = kD / 32;
    for (int it = 0; it < NIT; it++) {
        if (it + 1 < NIT) {
            int st = (it + 1) & 1, k0 = (it + 1) * 32;
            cp_async16(smem_u32(&As[st][lr][lc]),  &g_xn_h[(size_t)(m0 + lr) * kD + k0 + lc]);
            cp_async16(smem_u32(&As[st][lr2][lc]), &g_xn_h[(size_t)(m0 + lr2) * kD + k0 + lc]);
            cp_async16(smem_u32(&Bs[st][lr][lc]),  &g_wqkv_t[(size_t)(n0 + lr) * kD + k0 + lc]);
            cp_async16(smem_u32(&Bs[st][lr2][lc]), &g_wqkv_t[(size_t)(n0 + lr2) * kD + k0 + lc]);
            CP_COMMIT();
            CP_WAIT(1);
        } else {
            CP_WAIT(0);
        }
        __syncthreads();
        unsigned soff = (it & 1) * stageB;
        #pragma unroll
        for (int kb = 0; kb < 32; kb += 16) {
            unsigned a[4][4], b[2][4];
            #pragma unroll
            for (int mi = 0; mi < 4; mi++)
                ldsm_x4(a[mi], a_base + soff + (mi * 16 * 40 + kb) * 2);
            #pragma unroll
            for (int p = 0; p < 2; p++)
                ldsm_x4(b[p], b_base + soff + (p * 16 * 40 + kb) * 2);
            #pragma unroll
            for (int mi = 0; mi < 4; mi++)
                #pragma unroll
                for (int p = 0; p < 2; p++) {
                    mma16816(acc[mi][2 * p],     a[mi], b[p]);
                    mma16816(acc[mi][2 * p + 1], a[mi], b[p] + 2);
                }
        }
        __syncthreads();
    }
    // epilogue: scatter to q(+rw, *kQScale)/k/v (all coalesced __half2)
    #pragma unroll
    for (int mi = 0; mi < 4; mi++) {
        int r0e = m0 + wm * 64 + mi * 16 + gid, r1e = r0e + 8;
        int s0 = r0e >> 1, b0e = r0e & 1;
        int s1 = r1e >> 1, b1e = r1e & 1;
        #pragma unroll
        for (int ni = 0; ni < 4; ni++) {
            int c0 = n0 + wn * 32 + ni * 8 + tig * 2;
            int part = c0 >> 10, rem = c0 & 1023, hh = rem >> 6, d = rem & 63;
            size_t di0 = (((size_t)(b0e * kH + hh)) * kS + s0) * kDh + d;
            size_t di1 = (((size_t)(b1e * kH + hh)) * kS + s1) * kDh + d;
            float v00 = acc[mi][ni][0], v01 = acc[mi][ni][1];
            float v10 = acc[mi][ni][2], v11 = acc[mi][ni][3];
            if (part == 0) {
                float w0 = rw[rem], w1 = rw[rem + 1];
                *(__half2*)&g_q[di0] =
                    __floats2half2_rn((v00 + w0) * kQScale, (v01 + w1) * kQScale);
                *(__half2*)&g_q[di1] =
                    __floats2half2_rn((v10 + w0) * kQScale, (v11 + w1) * kQScale);
            } else if (part == 1) {
                *(__half2*)&g_k[di0] = __floats2half2_rn(v00, v01);
                *(__half2*)&g_k[di1] = __floats2half2_rn(v10, v11);
            } else {
                *(__half2*)&g_v[di0] = __floats2half2_rn(v00, v01);
                *(__half2*)&g_v[di1] = __floats2half2_rn(v10, v11);
            }
        }
    }
}

// ------------- Flash attention (fp16 mma, 128q/8warp, reg-Q/P, fused cbd) ----
// Block: 256 thr = 8 warps, one (b,h), 128 query rows (16/warp), key tiles 64.
// q pre-scaled by kScale*log2e: S and BD consts live in the log2 domain, so
// softmax uses ex2 directly (p = 2^(s'-m') = e^(s-m)).
__global__ __launch_bounds__(256) void flash_kernel(const float* __restrict__ rw,
                                                    const float* __restrict__ rr) {
    __shared__ __half Ks[2][64][72];
    __shared__ __half Vs[2][64][72];       // natural [j][d]
    __shared__ float csm[132];             // [0..128]=row dots (scaled), [130]=C_h
    int b = blockIdx.z, h = blockIdx.y, i0 = blockIdx.x * 128;
    int tid = threadIdx.x, w = tid >> 5, lane = tid & 31;
    int gid = lane >> 2, tig = lane & 3;
    size_t base = ((size_t)(b * kH + h)) * kS * kDh;

    // ---- stage Q through the K buffer (128 rows x 72 stride), capture -------
    __half* qstage = &Ks[0][0][0];
    #pragma unroll
    for (int t = 0; t < 4; t++) {
        int idx = tid + t * 256;
        int r = idx >> 3, c = (idx & 7) * 8;
        *(float4*)&qstage[r * 72 + c] = *(const float4*)&g_q[base + (size_t)(i0 + r) * kDh + c];
    }
    __syncthreads();
    unsigned qf[4][4];
    {
        unsigned qa = smem_u32(qstage + (w * 16 + (lane & 15)) * 72 + (lane >> 4) * 8);
        #pragma unroll
        for (int c4 = 0; c4 < 4; c4++) ldsm_x4(qf[c4], qa + c4 * 32);
    }
    // C_h = kQScale * sum_d (rr - rw) * rk0   (warp 0)
    if (w == 0) {
        int hd = h * kDh + lane;
        float chs = (rr[hd] - rw[hd]) * g_rk0[hd]
                  + (rr[hd + 32] - rw[hd + 32]) * g_rk0[hd + 32];
        #pragma unroll
        for (int o = 16; o; o >>= 1) chs += __shfl_xor_sync(~0u, chs, o);
        if (lane == 0) csm[130] = chs * kQScale;
    }
    // row dots: csm[r] = q_scaled_row . rk0  (pairs of threads per row)
    {
        int rrow = tid >> 1, halfsel = (tid & 1) * 32;
        const __half* qr = qstage + rrow * 72 + halfsel;
        const float* rk = g_rk0 + h * kDh + halfsel;
        float p = 0.f;
        #pragma unroll
        for (int d = 0; d < 32; d++) p += __half2float(qr[d]) * rk[d];
        p += __shfl_xor_sync(~0u, p, 1);
        if ((tid & 1) == 0) csm[rrow] = p;
    }
    // boundary row i0+128 (from gmem, already scaled)
    if (tid < 2) {
        int gi = i0 + 128;
        float p = 0.f;
        if (gi < kS) {
            const __half* qr = &g_q[base + (size_t)gi * kDh + tid * 32];
            const float* rk = g_rk0 + h * kDh + tid * 32;
            #pragma unroll
            for (int d = 0; d < 32; d++) p += __half2float(qr[d]) * rk[d];
        }
        p += __shfl_xor_sync(0x3u, p, 1);
        if (tid == 0) csm[128] = p;
    }
    __syncthreads();   // Q captured + csm ready; K buffer reusable

    float Ch = csm[130];
    int lr0 = w * 16 + gid;
    int r0 = i0 + lr0, r1 = r0 + 8;
    float cA  = csm[lr0] + Ch;
    float cA1 = (r0 + 1 < kS) ? csm[lr0 + 1] + Ch : 0.f;
    float cB  = csm[lr0 + 8] + Ch;
    float cB1 = (r1 + 1 < kS) ? csm[lr0 + 9] + Ch : 0.f;

    unsigned ka_base = smem_u32(&Ks[0][(lane & 7) + ((lane >> 4) << 3)][((lane >> 3) & 1) * 8]);
    unsigned va_base = smem_u32(&Vs[0][(lane & 7) + (((lane >> 3) & 1) << 3)][(lane >> 4) * 8]);
    constexpr unsigned stageB = 64 * 72 * 2;

    float m0v = -1e30f, m1v = -1e30f, l0 = 0.f, l1 = 0.f;
    float o[8][4] = {};

    // pipeline loader: 64 rows x 64 halfs = 512 chunks/array; 256 thr x 2 chunks
    int plr = tid >> 2, plc = (tid & 3) * 8;
    cp_async16(smem_u32(&Ks[0][plr][plc]),      &g_k[base + (size_t)plr * kDh + plc]);
    cp_async16(smem_u32(&Ks[0][plr][plc + 32]), &g_k[base + (size_t)plr * kDh + plc + 32]);
    cp_async16(smem_u32(&Vs[0][plr][plc]),      &g_v[base + (size_t)plr * kDh + plc]);
    cp_async16(smem_u32(&Vs[0][plr][plc + 32]), &g_v[base + (size_t)plr * kDh + plc + 32]);
    CP_COMMIT();

    constexpr int NT = kS / 64;
    for (int jt = 0; jt < NT; jt++) {
        if (jt + 1 < NT) {
            int st = (jt + 1) & 1;
            size_t roff = base + (size_t)((jt + 1) * 64 + plr) * kDh + plc;
            cp_async16(smem_u32(&Ks[st][plr][plc]),      &g_k[roff]);
            cp_async16(smem_u32(&Ks[st][plr][plc + 32]), &g_k[roff + 32]);
            cp_async16(smem_u32(&Vs[st][plr][plc]),      &g_v[roff]);
            cp_async16(smem_u32(&Vs[st][plr][plc + 32]), &g_v[roff + 32]);
            CP_COMMIT();
            CP_WAIT(1);
        } else {
            CP_WAIT(0);
        }
        __syncthreads();
        unsigned soff = (jt & 1) * stageB;
        int j0 = jt * 64;

        // S = Q K^T  (per warp: 16 x 64), scaled via q (log2 domain)
        float s[8][4] = {};
        #pragma unroll
        for (int c4 = 0; c4 < 4; c4++) {
            #pragma unroll
            for (int p = 0; p < 4; p++) {
                unsigned bb[4];
                ldsm_x4(bb, ka_base + soff + (p * 16 * 72 + c4 * 16) * 2);
                mma16816(s[2 * p],     qf[c4], bb);
                mma16816(s[2 * p + 1], qf[c4], bb + 2);
            }
        }

        // BD add: warp-uniform fast paths (tile fully before/after diagonal)
        float rmax0 = -1e30f, rmax1 = -1e30f;
        bool allA  = (j0 + 63) <= (i0 + w * 16);
        bool allA1 = j0 >= (i0 + w * 16 + 17);
        if (allA | allA1) {
            float b0 = allA ? cA : cA1;
            float b1 = allA ? cB : cB1;
            #pragma unroll
            for (int nt = 0; nt < 8; nt++) {
                s[nt][0] += b0; s[nt][1] += b0;
                s[nt][2] += b1; s[nt][3] += b1;
                rmax0 = fmaxf(rmax0, fmaxf(s[nt][0], s[nt][1]));
                rmax1 = fmaxf(rmax1, fmaxf(s[nt][2], s[nt][3]));
            }
        } else {
            #pragma unroll
            for (int nt = 0; nt < 8; nt++) {
                int gj = j0 + nt * 8 + tig * 2;
                float bd00 = (gj <= r0) ? cA : ((gj == r0 + 1) ? 0.f : cA1);
                float bd01 = (gj + 1 <= r0) ? cA : ((gj + 1 == r0 + 1) ? 0.f : cA1);
                float bd10 = (gj <= r1) ? cB : ((gj == r1 + 1) ? 0.f : cB1);
                float bd11 = (gj + 1 <= r1) ? cB : ((gj + 1 == r1 + 1) ? 0.f : cB1);
                s[nt][0] += bd00; s[nt][1] += bd01;
                s[nt][2] += bd10; s[nt][3] += bd11;
                rmax0 = fmaxf(rmax0, fmaxf(s[nt][0], s[nt][1]));
                rmax1 = fmaxf(rmax1, fmaxf(s[nt][2], s[nt][3]));
            }
        }
        rmax0 = fmaxf(rmax0, __shfl_xor_sync(~0u, rmax0, 1));
        rmax0 = fmaxf(rmax0, __shfl_xor_sync(~0u, rmax0, 2));
        rmax1 = fmaxf(rmax1, __shfl_xor_sync(~0u, rmax1, 1));
        rmax1 = fmaxf(rmax1, __shfl_xor_sync(~0u, rmax1, 2));
        float mn0 = fmaxf(m0v, rmax0), mn1 = fmaxf(m1v, rmax1);
        float al0 = fex2(m0v - mn0), al1 = fex2(m1v - mn1);
        // P = 2^(s - mn) via f16x2 ex2; lands directly in MMA A-fragment format
        unsigned ph0[8], ph1[8];
        #pragma unroll
        for (int nt = 0; nt < 8; nt++) {
            __half2 t0 = __floats2half2_rn(s[nt][0] - mn0, s[nt][1] - mn0);
            __half2 t1 = __floats2half2_rn(s[nt][2] - mn1, s[nt][3] - mn1);
            ph0[nt] = h2ex2(*(unsigned*)&t0);
            ph1[nt] = h2ex2(*(unsigned*)&t1);
        }
        __half2 ha0 = *(__half2*)&ph0[0], ha1 = *(__half2*)&ph1[0];
        #pragma unroll
        for (int nt = 1; nt < 8; nt++) {
            ha0 = __hadd2(ha0, *(__half2*)&ph0[nt]);
            ha1 = __hadd2(ha1, *(__half2*)&ph1[nt]);
        }
        float rs0 = __low2float(ha0) + __high2float(ha0);
        float rs1 = __low2float(ha1) + __high2float(ha1);
        rs0 += __shfl_xor_sync(~0u, rs0, 1);
        rs0 += __shfl_xor_sync(~0u, rs0, 2);
        rs1 += __shfl_xor_sync(~0u, rs1, 1);
        rs1 += __shfl_xor_sync(~0u, rs1, 2);
        l0 = l0 * al0 + rs0; l1 = l1 * al1 + rs1;
        m0v = mn0; m1v = mn1;
        #pragma unroll
        for (int nt = 0; nt < 8; nt++) {
            o[nt][0] *= al0; o[nt][1] *= al0;
            o[nt][2] *= al1; o[nt][3] *= al1;
        }

        // O += P V   (A from regs; B via ldmatrix.trans on natural V[j][d])
        #pragma unroll
        for (int c4 = 0; c4 < 4; c4++) {
            unsigned a[4] = { ph0[2 * c4], ph1[2 * c4], ph0[2 * c4 + 1], ph1[2 * c4 + 1] };
            #pragma unroll
            for (int p = 0; p < 4; p++) {
                unsigned bb[4];
                ldsm_x4_trans(bb, va_base + soff + (c4 * 16 * 72 + p * 16) * 2);
                mma16816(o[2 * p],     a, bb);
                mma16816(o[2 * p + 1], a, bb + 2);
            }
        }
        __syncthreads();
    }

    float inv0 = 1.f / l0, inv1 = 1.f / l1;
    #pragma unroll
    for (int nt = 0; nt < 8; nt++) {
        int d = nt * 8 + tig * 2;
        *(__half2*)&g_av[((size_t)r0 * kB + b) * kD + h * kDh + d] =
            __floats2half2_rn(o[nt][0] * inv0, o[nt][1] * inv0);
        *(__half2*)&g_av[((size_t)r1 * kB + b) * kD + h * kDh + d] =
            __floats2half2_rn(o[nt][2] * inv1, o[nt][3] * inv1);
    }
}

// ---------------------- Output GEMM + residual (fp16 mma) --------------------
__global__ __launch_bounds__(256) void gemm_out_kernel(float* __restrict__ out) {
    __shared__ __half As[2][128][40];
    __shared__ __half Bs[2][128][40];
    int tid = threadIdx.x, lane = tid & 31, w = tid >> 5;
    int gid = lane >> 2, tig = lane & 3;
    int m0 = blockIdx.y * 128, n0 = blockIdx.x * 128;
    int wm = w >> 2, wn = w & 3;
    constexpr unsigned stageB = 128 * 40 * 2;
    unsigned a_base = smem_u32(&As[0][wm * 64 + (lane & 15)][(lane >> 4) * 8]);
    unsigned b_base = smem_u32(&Bs[0][wn * 32 + (lane & 7) + ((lane >> 4) << 3)][((lane >> 3) & 1) * 8]);
    int lr = tid >> 2, lc = (tid & 3) * 8;
    int lr2 = lr + 64;
    float acc[4][4][4] = {};

    cp_async16(smem_u32(&As[0][lr][lc]),  &g_av[(size_t)(m0 + lr) * kD + lc]);
    cp_async16(smem_u32(&As[0][lr2][lc]), &g_av[(size_t)(m0 + lr2) * kD + lc]);
    cp_async16(smem_u32(&Bs[0][lr][lc]),  &g_wo_t[(size_t)(n0 + lr) * kD + lc]);
    cp_async16(smem_u32(&Bs[0][lr2][lc]), &g_wo_t[(size_t)(n0 + lr2) * kD + lc]);
    CP_COMMIT();

    constexpr int NIT = kD / 32;
    for (int it = 0; it < NIT; it++) {
        if (it + 1 < NIT) {
            int st = (it + 1) & 1, k0 = (it + 1) * 32;
            cp_async16(smem_u32(&As[st][lr][lc]),  &g_av[(size_t)(m0 + lr) * kD + k0 + lc]);
            cp_async16(smem_u32(&As[st][lr2][lc]), &g_av[(size_t)(m0 + lr2) * kD + k0 + lc]);
            cp_async16(smem_u32(&Bs[st][lr][lc]),  &g_wo_t[(size_t)(n0 + lr) * kD + k0 + lc]);
            cp_async16(smem_u32(&Bs[st][lr2][lc]), &g_wo_t[(size_t)(n0 + lr2) * kD + k0 + lc]);
            CP_COMMIT();
            CP_WAIT(1);
        } else {
            CP_WAIT(0);
        }
        __syncthreads();
        unsigned soff = (it & 1) * stageB;
        #pragma unroll
        for (int kb = 0; kb < 32; kb += 16) {
            unsigned a[4][4], b[2][4];
            #pragma unroll
            for (int mi = 0; mi < 4; mi++)
                ldsm_x4(a[mi], a_base + soff + (mi * 16 * 40 + kb) * 2);
            #pragma unroll
            for (int p = 0; p < 2; p++)
                ldsm_x4(b[p], b_base + soff + (p * 16 * 40 + kb) * 2);
            #pragma unroll
            for (int mi = 0; mi < 4; mi++)
                #pragma unroll
                for (int p = 0; p < 2; p++) {
                    mma16816(acc[mi][2 * p],     a[mi], b[p]);
                    mma16816(acc[mi][2 * p + 1], a[mi], b[p] + 2);
                }
        }
        __syncthreads();
    }
    #pragma unroll
    for (int mi = 0; mi < 4; mi++) {
        int r0e = m0 + wm * 64 + mi * 16 + gid, r1e = r0e + 8;
        #pragma unroll
        for (int ni = 0; ni < 4; ni++) {
            int c0 = n0 + wn * 32 + ni * 8 + tig * 2;
            float2 x0 = *(const float2*)&g_xn[(size_t)r0e * kD + c0];
            float2 x1 = *(const float2*)&g_xn[(size_t)r1e * kD + c0];
            float2 o0 = { acc[mi][ni][0] + x0.x, acc[mi][ni][1] + x0.y };
            float2 o1 = { acc[mi][ni][2] + x1.x, acc[mi][ni][3] + x1.y };
            *(float2*)&out[(size_t)r0e * kD + c0] = o0;
            *(float2*)&out[(size_t)r1e * kD + c0] = o1;
        }
    }
}

// --------------------------------- launch ------------------------------------
extern "C" void kernel_launch(void* const* d_in, const int* in_sizes, int n_in,
                              void* d_out, int out_size) {
    const float* x    = (const float*)d_in[0];
    const float* r    = (const float*)d_in[1];
    const float* rw   = (const float*)d_in[2];
    const float* rr   = (const float*)d_in[3];
    const float* ln_g = (const float*)d_in[4];
    const float* ln_b = (const float*)d_in[5];
    const float* Wqkv = (const float*)d_in[6];
    const float* Wr   = (const float*)d_in[7];
    const float* Wo   = (const float*)d_in[8];
    float* out = (float*)d_out;

    prologue_kernel<<<kNbLn + kNbCw0 + kNbCw1 + kNbRk, 256>>>(x, ln_g, ln_b, Wqkv, Wo, r, Wr);
    rk0_reduce_kernel<<<kD / 256, 256>>>();
    gemm_qkv_kernel<<<dim3(3 * kD / 128, kRows / 128), 256>>>(rw);
    flash_kernel<<<dim3(kS / 128, kH, kB), 256>>>(rw, rr);
    gemm_out_kernel<<<dim3(kD / 128, kRows / 128), 256>>>(out);
}